// round 1
// baseline (speedup 1.0000x reference)
#include <cuda_runtime.h>
#include <cstdint>

// FrequencyEnhancement: out = x + gate*(x - y_low), y_low = IDCT(truncate_M(DCT(x)))
// N=4096 per row, M=N/4=1024 kept coeffs. 32*512=16384 rows.
//
// Per row: real-4096 DCT via packed complex FFT-2048 -> spectral middle step
// (only k<1024 survive) -> inverse FFT-2048 (conj trick) -> un-permute + fuse.

#define NN    4096
#define NH    2048
#define TPB   256
#define NROWS 16384

__device__ float2 d_W[NH];       // e^{-2*pi*i*j/2048}
__device__ float4 d_mid[1024];   // (cos t, sin t, cos 4t, sin 4t), t = pi*k/8192

__global__ void init_tables_kernel() {
    int i = blockIdx.x * blockDim.x + threadIdx.x;
    const double PI = 3.14159265358979323846;
    if (i < NH) {
        double a = -2.0 * PI * (double)i / (double)NH;
        d_W[i] = make_float2((float)cos(a), (float)sin(a));
    }
    if (i < 1024) {
        double t = PI * (double)i / 8192.0;
        d_mid[i] = make_float4((float)cos(t), (float)sin(t),
                               (float)cos(4.0 * t), (float)sin(4.0 * t));
    }
}

__device__ __forceinline__ float2 cmul(float2 a, float2 b) {
    return make_float2(a.x * b.x - a.y * b.y, a.x * b.y + a.y * b.x);
}
__device__ __forceinline__ float2 cadd(float2 a, float2 b) {
    return make_float2(a.x + b.x, a.y + b.y);
}
__device__ __forceinline__ float2 csub(float2 a, float2 b) {
    return make_float2(a.x - b.x, a.y - b.y);
}

// Stockham autosort forward FFT, length 2048 = 4^5 * 2.
// Input in bA. Result ends in bA (6 stages, even number of ping-pongs).
__device__ __forceinline__ void fft2048(float2* bA, float2* bB, int t) {
    float2* src = bA;
    float2* dst = bB;
#pragma unroll
    for (int stage = 0; stage < 5; stage++) {
        const int s  = 1 << (2 * stage);       // 1,4,16,64,256
#pragma unroll
        for (int u0 = 0; u0 < 2; u0++) {
            int u = u0 * TPB + t;              // u in [0,512)
            int p = u / s;
            int q = u - p * s;
            float2 w1 = d_W[p * s];            // e^{-2pi i * p*s / 2048}
            float2 w2 = cmul(w1, w1);
            float2 w3 = cmul(w2, w1);
            int base = q + s * p;              // == u
            float2 a = src[base];
            float2 b = src[base + 512];        // s*m == 512 at every stage
            float2 c = src[base + 1024];
            float2 d = src[base + 1536];
            float2 apc = cadd(a, c);
            float2 amc = csub(a, c);
            float2 bpd = cadd(b, d);
            float2 bmd = csub(b, d);
            float2 jbmd = make_float2(-bmd.y, bmd.x);   // i*(b-d)
            int ob = q + 4 * s * p;
            dst[ob]         = cadd(apc, bpd);
            dst[ob + s]     = cmul(w1, csub(amc, jbmd));
            dst[ob + 2*s]   = cmul(w2, csub(apc, bpd));
            dst[ob + 3*s]   = cmul(w3, cadd(amc, jbmd));
        }
        __syncthreads();
        float2* tmp = src; src = dst; dst = tmp;
    }
    // final radix-2 stage: n=2, s=1024, twiddle = 1
#pragma unroll
    for (int u0 = 0; u0 < 4; u0++) {
        int u = u0 * TPB + t;                  // [0,1024)
        float2 a = src[u];
        float2 b = src[u + 1024];
        dst[u]        = cadd(a, b);
        dst[u + 1024] = csub(a, b);
    }
    __syncthreads();
    // src started as bA; after 5 swaps src==bB, dst==bA -> result in bA.
}

__global__ __launch_bounds__(TPB)
void freq_enh_kernel(const float* __restrict__ x,
                     const float* __restrict__ gate,
                     float* __restrict__ out) {
    __shared__ float2 bufA[NH];
    __shared__ float2 bufB[NH];

    const int row = blockIdx.x;
    const int t   = threadIdx.x;
    const float* px = x + (size_t)row * NN;
    float*      po  = out + (size_t)row * NN;
    const float gv  = __ldg(&gate[row]);

    // Stage x into smem (bufB as float[4096]) and keep in registers.
    float xr[16];
    float* xs = reinterpret_cast<float*>(bufB);
#pragma unroll
    for (int i = 0; i < 16; i++) {
        float v = px[i * TPB + t];
        xr[i] = v;
        xs[i * TPB + t] = v;
    }
    __syncthreads();

    // Build packed sequence z[m] = v[2m] + i*v[2m+1] into bufA,
    // where v = concat(x[::2], flip(x[1::2])).
#pragma unroll
    for (int i = 0; i < 8; i++) {
        int m = i * TPB + t;                   // [0,2048)
        float re = (m < 1024) ? xs[4 * m]     : xs[8191 - 4 * m];
        float im = (m < 1024) ? xs[4 * m + 2] : xs[8189 - 4 * m];
        bufA[m] = make_float2(re, im);
    }
    __syncthreads();

    // Forward FFT: Z in bufA.
    fft2048(bufA, bufB, t);

    // Middle step: unpack real spectrum, DCT twiddle, truncate at M=1024,
    // build conj(G) for the inverse (conj-FFT-conj trick) into bufB.
#pragma unroll
    for (int i = 0; i < 4; i++) {
        int k = i * TPB + t;                   // [0,1024)
        float2 Zk = bufA[k];
        float2 Zj = bufA[(NH - k) & (NH - 1)];
        float4 md = d_mid[k];                  // (c, s, c4, s4)
        // even/odd split of the real length-4096 FFT
        float Ex = 0.5f * (Zk.x + Zj.x);
        float Ey = 0.5f * (Zk.y - Zj.y);
        float Ox = 0.5f * (Zk.y + Zj.y);
        float Oy = -0.5f * (Zk.x - Zj.x);
        // Vc_k = E + e^{-i*4t} * O     (4t = 2*pi*k/4096)
        float WOx = md.z * Ox + md.w * Oy;
        float WOy = md.z * Oy - md.w * Ox;
        float Vcx = Ex + WOx;
        float Vcy = Ey + WOy;
        // V_k = Re(Vc * e^{-i t})  (real DCT value, ortho factors cancel)
        float V = Vcx * md.x + Vcy * md.y;
        // H_k = V * e^{+i t}
        float Hx = V * md.x;
        float Hy = V * md.y;
        // G_k       = 0.5 * H * ((1 - s4) + i c4)
        // G_{2048-k}= conj(0.5 * H * ((1 + s4) - i c4))
        float g1 = 0.5f * (1.0f - md.w), g2 = 0.5f * md.z;
        float Gkx = Hx * g1 - Hy * g2;
        float Gky = Hx * g2 + Hy * g1;
        bufB[k] = make_float2(Gkx, -Gky);      // conj(G_k)
        if (k > 0) {
            float h1 = 0.5f * (1.0f + md.w), h2 = -0.5f * md.z;
            float Gmx = Hx * h1 - Hy * h2;
            float Gmy = Hx * h2 + Hy * h1;
            bufB[NH - k] = make_float2(Gmx, Gmy);  // conj(G_{2048-k})
        } else {
            bufB[1024] = make_float2(0.0f, 0.0f);
        }
    }
    __syncthreads();

    // Inverse FFT via conjugation: R = FFT_fwd(conj(G)); z' = conj(R)/2048.
    fft2048(bufB, bufA, t);

    // Fuse: out = x + gate * (x - y_low), with output un-permutation.
    const float inv = 1.0f / 2048.0f;
#pragma unroll
    for (int i = 0; i < 16; i++) {
        int idx = i * TPB + t;
        int j = (idx & 1) ? (NN - 1 - (idx >> 1)) : (idx >> 1);
        float2 r = bufB[j >> 1];
        float y = (j & 1) ? (-r.y * inv) : (r.x * inv);
        po[idx] = xr[i] + gv * (xr[i] - y);
    }
}

extern "C" void kernel_launch(void* const* d_in, const int* in_sizes, int n_in,
                              void* d_out, int out_size) {
    const float* x    = (const float*)d_in[0];
    const float* gate = (const float*)d_in[1];
    float* out        = (float*)d_out;
    init_tables_kernel<<<8, 256>>>();
    freq_enh_kernel<<<NROWS, TPB>>>(x, gate, out);
}

// round 4
// speedup vs baseline: 1.0785x; 1.0785x over previous
#include <cuda_runtime.h>
#include <cstdint>

// out = x + gate*(x - y_low), y_low = IDCT(truncate_{N/4}(DCT(x))), N=4096.
// Per row: packed real-4096 DCT via FFT-2048 -> spectral middle -> inverse
// FFT-2048 (conj trick). Register-resident radix-8 FFT: 3 smem exchanges/FFT,
// separate re/im arrays padded with i+(i>>3) for (near) conflict-free access.

#define NN    4096
#define NH    2048
#define TPB   256
#define NROWS 16384
#define PAD(i) ((i) + ((i) >> 3))

__device__ float2 d_W[NH];       // e^{-2*pi*i*j/2048}
__device__ float4 d_mid[1024];   // (cos t, sin t, cos 4t, sin 4t), t = pi*k/8192

__global__ void init_tables_kernel() {
    int i = blockIdx.x * blockDim.x + threadIdx.x;
    const double PI = 3.14159265358979323846;
    if (i < NH) {
        double a = -2.0 * PI * (double)i / (double)NH;
        d_W[i] = make_float2((float)cos(a), (float)sin(a));
    }
    if (i < 1024) {
        double t = PI * (double)i / 8192.0;
        d_mid[i] = make_float4((float)cos(t), (float)sin(t),
                               (float)cos(4.0 * t), (float)sin(4.0 * t));
    }
}

__device__ __forceinline__ float2 cmul(float2 a, float2 b) {
    return make_float2(a.x * b.x - a.y * b.y, a.x * b.y + a.y * b.x);
}
__device__ __forceinline__ float2 cadd(float2 a, float2 b) {
    return make_float2(a.x + b.x, a.y + b.y);
}
__device__ __forceinline__ float2 csub(float2 a, float2 b) {
    return make_float2(a.x - b.x, a.y - b.y);
}

// One Stockham radix-8 stage at span S (in-place over padded SR/SI).
// Caller guarantees data is visible (sync before entry); trailing sync inside.
template<int S>
__device__ __forceinline__ void stage8(float* __restrict__ SRp,
                                       float* __restrict__ SIp, int t) {
    float2 a[8];
#pragma unroll
    for (int j = 0; j < 8; j++) {
        int m = t + 256 * j;
        a[j] = make_float2(SRp[PAD(m)], SIp[PAD(m)]);
    }
    __syncthreads();

    const int p = t / S, q = t - p * S;
    float2 w1 = d_W[S * p];

    const float C = 0.70710678118654752440f;
    // DIF level 1 (span 4) + W8^j on the lower half
    float2 s0 = cadd(a[0], a[4]), s1 = cadd(a[1], a[5]);
    float2 s2 = cadd(a[2], a[6]), s3 = cadd(a[3], a[7]);
    float2 d0 = csub(a[0], a[4]), d1 = csub(a[1], a[5]);
    float2 d2 = csub(a[2], a[6]), d3 = csub(a[3], a[7]);
    float2 d1t = make_float2(C * (d1.x + d1.y), C * (d1.y - d1.x));   // *W8^1
    float2 d2t = make_float2(d2.y, -d2.x);                            // *W8^2
    float2 d3t = make_float2(C * (d3.y - d3.x), -C * (d3.x + d3.y));  // *W8^3
    // even outputs: DFT4 of (s0..s3) -> X0,X2,X4,X6
    float2 m0 = cadd(s0, s2), m1 = cadd(s1, s3);
    float2 n0 = csub(s0, s2);
    float2 tt = csub(s1, s3);
    float2 n1 = make_float2(tt.y, -tt.x);                             // *(-i)
    float2 X0 = cadd(m0, m1), X4 = csub(m0, m1);
    float2 X2 = cadd(n0, n1), X6 = csub(n0, n1);
    // odd outputs: DFT4 of (d0,d1t,d2t,d3t) -> X1,X3,X5,X7
    float2 p0 = cadd(d0, d2t), p1 = cadd(d1t, d3t);
    float2 q0 = csub(d0, d2t);
    float2 uu = csub(d1t, d3t);
    float2 q1 = make_float2(uu.y, -uu.x);
    float2 X1 = cadd(p0, p1), X5 = csub(p0, p1);
    float2 X3 = cadd(q0, q1), X7 = csub(q0, q1);

    float2 w2 = cmul(w1, w1), w3 = cmul(w2, w1), w4 = cmul(w2, w2);
    float2 w5 = cmul(w2, w3), w6 = cmul(w3, w3), w7 = cmul(w3, w4);

    const int ob = q + 8 * S * p;
#define ST8(r, v) { float2 _v = (v); int _i = PAD(ob + S * (r)); SRp[_i] = _v.x; SIp[_i] = _v.y; }
    ST8(0, X0); ST8(1, cmul(w1, X1)); ST8(2, cmul(w2, X2)); ST8(3, cmul(w3, X3));
    ST8(4, cmul(w4, X4)); ST8(5, cmul(w5, X5)); ST8(6, cmul(w6, X6)); ST8(7, cmul(w7, X7));
#undef ST8
    __syncthreads();
}

// Final radix-4 stage (span 512, unit twiddles), two butterflies per thread.
__device__ __forceinline__ void stage4_final(float* __restrict__ SRp,
                                             float* __restrict__ SIp, int t) {
    float2 a[8];
#pragma unroll
    for (int h = 0; h < 2; h++)
#pragma unroll
        for (int j = 0; j < 4; j++) {
            int m = t + 256 * h + 512 * j;
            a[h * 4 + j] = make_float2(SRp[PAD(m)], SIp[PAD(m)]);
        }
    __syncthreads();
#pragma unroll
    for (int h = 0; h < 2; h++) {
        int u = t + 256 * h;
        float2 a0 = a[h * 4], a1 = a[h * 4 + 1], a2 = a[h * 4 + 2], a3 = a[h * 4 + 3];
        float2 b0 = cadd(a0, a2), b1 = csub(a0, a2);
        float2 b2 = cadd(a1, a3), b3 = csub(a1, a3);
        float2 jb3 = make_float2(-b3.y, b3.x);          // i*(a1-a3)
        float2 X0 = cadd(b0, b2), X2 = csub(b0, b2);
        float2 X1 = csub(b1, jb3), X3 = cadd(b1, jb3);
        int i0;
        i0 = PAD(u);        SRp[i0] = X0.x; SIp[i0] = X0.y;
        i0 = PAD(u + 512);  SRp[i0] = X1.x; SIp[i0] = X1.y;
        i0 = PAD(u + 1024); SRp[i0] = X2.x; SIp[i0] = X2.y;
        i0 = PAD(u + 1536); SRp[i0] = X3.x; SIp[i0] = X3.y;
    }
    __syncthreads();
}

__global__ __launch_bounds__(TPB, 3)
void freq_enh_kernel(const float* __restrict__ x,
                     const float* __restrict__ gate,
                     float* __restrict__ out) {
    __shared__ float SR[2304];
    __shared__ float SI[2304];

    const int row = blockIdx.x;
    const int t   = threadIdx.x;
    const float* px = x + (size_t)row * NN;
    float*      po  = out + (size_t)row * NN;
    const float gv  = __ldg(&gate[row]);

    // Load x into registers; scatter the packed sequence z into SR/SI.
    // v = concat(x[::2], flip(x[1::2])); z[m] = v[2m] + i v[2m+1].
    float xr[16];
#pragma unroll
    for (int i = 0; i < 16; i++) {
        int idx = i * TPB + t;
        float v = px[idx];
        xr[i] = v;
        int n = (idx & 1) ? ((8191 - idx) >> 1) : (idx >> 1);   // position in v
        int m = n >> 1;
        if (n & 1) SI[PAD(m)] = v; else SR[PAD(m)] = v;
    }
    __syncthreads();

    // Forward FFT-2048
    stage8<1>(SR, SI, t);
    stage8<8>(SR, SI, t);
    stage8<64>(SR, SI, t);
    stage4_final(SR, SI, t);

    // Middle: unpack real spectrum, DCT twiddle, truncate at M=1024,
    // write conj(G) in place (disjoint {k, 2048-k} pairs per thread).
#pragma unroll
    for (int i = 0; i < 4; i++) {
        int k  = i * TPB + t;                 // [0,1024)
        int kp = PAD(k);
        int km = (NH - k) & (NH - 1);
        int kmp = PAD(km);
        float Zkx = SR[kp], Zky = SI[kp];
        float Zjx = SR[kmp], Zjy = SI[kmp];
        float4 md = d_mid[k];                 // (c, s, c4, s4)
        float Ex = 0.5f * (Zkx + Zjx);
        float Ey = 0.5f * (Zky - Zjy);
        float Ox = 0.5f * (Zky + Zjy);
        float Oy = -0.5f * (Zkx - Zjx);
        float WOx = md.z * Ox + md.w * Oy;
        float WOy = md.z * Oy - md.w * Ox;
        float Vcx = Ex + WOx;
        float Vcy = Ey + WOy;
        float V  = Vcx * md.x + Vcy * md.y;   // real DCT bin (ortho factors cancel)
        float Hx = V * md.x, Hy = V * md.y;
        float g1 = 0.5f * (1.0f - md.w), g2 = 0.5f * md.z;
        SR[kp] = Hx * g1 - Hy * g2;
        SI[kp] = -(Hx * g2 + Hy * g1);        // conj(G_k)
        if (k > 0) {
            float h1 = 0.5f * (1.0f + md.w), h2 = -0.5f * md.z;
            SR[kmp] = Hx * h1 - Hy * h2;      // conj(G_{2048-k}) (already conj form)
            SI[kmp] = Hx * h2 + Hy * h1;
        } else {
            SR[PAD(1024)] = 0.0f; SI[PAD(1024)] = 0.0f;
        }
    }
    __syncthreads();

    // Inverse FFT via conjugation: R = FFT(conj(G)); z' = conj(R)/2048.
    stage8<1>(SR, SI, t);
    stage8<8>(SR, SI, t);
    stage8<64>(SR, SI, t);
    stage4_final(SR, SI, t);

    // Fuse: out = x + gate * (x - y_low), un-permuting the DCT output order.
    const float inv = 1.0f / 2048.0f;
#pragma unroll
    for (int i = 0; i < 16; i++) {
        int idx = i * TPB + t;
        int j = (idx & 1) ? (NN - 1 - (idx >> 1)) : (idx >> 1);
        int jp = PAD(j >> 1);
        float y = (j & 1) ? (-SI[jp] * inv) : (SR[jp] * inv);
        po[idx] = xr[i] + gv * (xr[i] - y);
    }
}

extern "C" void kernel_launch(void* const* d_in, const int* in_sizes, int n_in,
                              void* d_out, int out_size) {
    const float* x    = (const float*)d_in[0];
    const float* gate = (const float*)d_in[1];
    float* out        = (float*)d_out;
    init_tables_kernel<<<8, 256>>>();
    freq_enh_kernel<<<NROWS, TPB>>>(x, gate, out);
}